// round 15
// baseline (speedup 1.0000x reference)
#include <cuda_runtime.h>
#include <cuda_bf16.h>
#include <math.h>
#include <cstdint>

// Problem constants
#define Bb   2
#define Ss   2048
#define Dd   768
#define Hh   12
#define DHd  64
#define Tt   64
#define FFd  3072
#define Rr   50

#define MTOT (Bb*Ss)        // 4096

// ---------------- scratch (device globals; no allocations allowed) ----------
__device__ float g_t1 [MTOT*Dd];
__device__ float g_x1 [MTOT*Dd];
__device__ float g_x2 [MTOT*Dd];
__device__ float g_b3 [3*Dd];

// bf16 hi/lo buffers
__device__ __nv_bfloat16 g_xh [MTOT*Dd],  g_xl [MTOT*Dd];
__device__ __nv_bfloat16 g_x1h[MTOT*Dd],  g_x1l[MTOT*Dd];
__device__ __nv_bfloat16 g_x2h[MTOT*Dd],  g_x2l[MTOT*Dd];
__device__ __nv_bfloat16 g_cth[MTOT*Dd],  g_ctl[MTOT*Dd];
__device__ __nv_bfloat16 g_ffh[MTOT*FFd], g_ffl[MTOT*FFd];
__device__ __nv_bfloat16 g_tgh[Tt*Dd],    g_tgl[Tt*Dd];
__device__ __nv_bfloat16 g_qh [MTOT*Dd],  g_ql [MTOT*Dd];
__device__ __nv_bfloat16 g_kh [MTOT*Dd],  g_kl [MTOT*Dd];
__device__ __nv_bfloat16 g_vth[Dd*MTOT],  g_vtl[Dd*MTOT];   // V^T [n][m]
__device__ __nv_bfloat16 g_ckh[Tt*Dd],    g_ckl[Tt*Dd];
__device__ __nv_bfloat16 g_cvth[Dd*Tt],   g_cvtl[Dd*Tt];    // cross V^T

// transposed weights [N][K] hi/lo; wq,wk,wv contiguous -> fused QKV B = [2304][768]
#define WSZ  (Dd*Dd)
#define WOFF_FF1 (8*WSZ)
#define WOFF_FF2 (WOFF_FF1 + Dd*FFd)
#define WTOT (WOFF_FF2 + FFd*Dd)
__device__ __nv_bfloat16 g_wh[WTOT], g_wl[WTOT];

// =============== helpers =====================================================
__device__ __forceinline__ void mma16816(float* c, const uint32_t* a, const uint32_t* b) {
    asm volatile(
        "mma.sync.aligned.m16n8k16.row.col.f32.bf16.bf16.f32 "
        "{%0,%1,%2,%3}, {%4,%5,%6,%7}, {%8,%9}, {%0,%1,%2,%3};\n"
        : "+f"(c[0]), "+f"(c[1]), "+f"(c[2]), "+f"(c[3])
        : "r"(a[0]), "r"(a[1]), "r"(a[2]), "r"(a[3]), "r"(b[0]), "r"(b[1]));
}
__device__ __forceinline__ void ldsm4(uint32_t* r, uint32_t addr) {
    asm volatile("ldmatrix.sync.aligned.m8n8.x4.shared.b16 {%0,%1,%2,%3}, [%4];"
                 : "=r"(r[0]), "=r"(r[1]), "=r"(r[2]), "=r"(r[3]) : "r"(addr));
}
__device__ __forceinline__ uint32_t pack_bf2(__nv_bfloat16 a, __nv_bfloat16 b) {
    return ((uint32_t)__bfloat16_as_ushort(b) << 16) | (uint32_t)__bfloat16_as_ushort(a);
}
__device__ __forceinline__ uint32_t smem_u32(const void* p) {
    uint32_t a;
    asm("{ .reg .u64 t; cvta.to.shared.u64 t, %1; cvt.u32.u64 %0, t; }" : "=r"(a) : "l"(p));
    return a;
}
__device__ __forceinline__ void cpa16(uint32_t dst, const void* src, bool valid) {
    int sz = valid ? 16 : 0;
    asm volatile("cp.async.cg.shared.global [%0], [%1], 16, %2;"
                 :: "r"(dst), "l"(src), "r"(sz));
}
#define CP_COMMIT() asm volatile("cp.async.commit_group;" ::: "memory")
#define CP_WAIT(n)  asm volatile("cp.async.wait_group %0;" :: "n"(n) : "memory")

__device__ __forceinline__ void split_bf(float v, __nv_bfloat16& h, __nv_bfloat16& l) {
    h = __float2bfloat16(v);
    l = __float2bfloat16(v - __bfloat162float(h));
}

// ============ conversion kernels ============================================
__global__ void fconv(const float* __restrict__ x, __nv_bfloat16* __restrict__ h,
                      __nv_bfloat16* __restrict__ l, int n4)
{
    int i = blockIdx.x * 256 + threadIdx.x;
    if (i >= n4) return;
    float4 v = ((const float4*)x)[i];
    __nv_bfloat16 h0,h1,h2,h3,l0,l1,l2,l3;
    split_bf(v.x,h0,l0); split_bf(v.y,h1,l1); split_bf(v.z,h2,l2); split_bf(v.w,h3,l3);
    ((uint2*)h)[i] = make_uint2(pack_bf2(h0,h1), pack_bf2(h2,h3));
    ((uint2*)l)[i] = make_uint2(pack_bf2(l0,l1), pack_bf2(l2,l3));
}

__global__ void bcat3(const float* __restrict__ b0, const float* __restrict__ b1,
                      const float* __restrict__ b2, float* __restrict__ o)
{
    int i = blockIdx.x * 256 + threadIdx.x;
    if (i < Dd)            o[i] = b0[i];
    else if (i < 2*Dd)     o[i] = b1[i - Dd];
    else if (i < 3*Dd)     o[i] = b2[i - 2*Dd];
}

// fused weight transpose+split for all 10 weights in one launch
struct WAll {
    const float* W[10];
    __nv_bfloat16* Wh[10];
    __nv_bfloat16* Wl[10];
    int K[10], N[10], t0[10];
};

__global__ void wtconv_all(WAll d)
{
    __shared__ float t[32][33];
    const int bid = blockIdx.x;
    int w = 0;
    #pragma unroll
    for (int i = 1; i < 10; i++) if (bid >= d.t0[i]) w = i;
    const int K = d.K[w], N = d.N[w];
    const int tloc = bid - d.t0[w];
    const int nx = N >> 5;
    const int n0 = (tloc % nx) * 32, k0 = (tloc / nx) * 32;
    const float* W = d.W[w];
    __nv_bfloat16* Wh = d.Wh[w];
    __nv_bfloat16* Wl = d.Wl[w];

    const int tx = threadIdx.x, ty = threadIdx.y;   // 32 x 8
    #pragma unroll
    for (int i = 0; i < 4; i++)
        t[ty + i*8][tx] = W[(long)(k0 + ty + i*8) * N + n0 + tx];
    __syncthreads();
    #pragma unroll
    for (int i = 0; i < 4; i++) {
        int n = n0 + ty + i*8;
        float v = t[tx][ty + i*8];
        __nv_bfloat16 h, l; split_bf(v, h, l);
        Wh[(long)n * K + k0 + tx] = h;
        Wl[(long)n * K + k0 + tx] = l;
    }
}

// ======== split-bf16 tensor-core GEMM ========================================
// 256 threads, 8 warps (2x4), warp tile 64x32, CTA tile 128x128, BK=32.
// 3-stage cp.async ring -> ONE __syncthreads per K-chunk.
// OMODE: 0 = fp32 C, 1 = bf16 hi/lo, 2 = bf16 hi/lo TRANSPOSED [n][m] (ldt)
#define STG_B 40960

template<int ACT, int RES, int OMODE>
__global__ void __launch_bounds__(256)
gemm_bf(const __nv_bfloat16* __restrict__ Ahp, const __nv_bfloat16* __restrict__ Alp,
        const __nv_bfloat16* __restrict__ Bhp, const __nv_bfloat16* __restrict__ Blp,
        const float* __restrict__ bias, const float* __restrict__ Rz,
        float* __restrict__ C, __nv_bfloat16* __restrict__ Chp, __nv_bfloat16* __restrict__ Clp,
        int M, int N, int K, int ldt)
{
    extern __shared__ char smem[];
    const uint32_t sb = smem_u32(smem);
    const int tid  = threadIdx.x;
    const int lane = tid & 31;
    const int wid  = tid >> 5;
    const int wm   = (wid & 1) * 64;
    const int wn   = (wid >> 1) * 32;
    const int bm   = blockIdx.y * 128;
    const int bn   = blockIdx.x * 128;
    const int nch  = K >> 5;
    const int gq = lane >> 2;
    const int gt = lane & 3;

    const int lrow = lane & 7, lmat = lane >> 3;
    const uint32_t aoff = (uint32_t)((lrow + (lmat & 1) * 8) * 80 + (lmat >> 1) * 16);
    const uint32_t boff = (uint32_t)((lrow + (lmat >> 1) * 8) * 80 + (lmat & 1) * 16);

    float acc[4][4][4];
    #pragma unroll
    for (int i = 0; i < 4; i++)
        #pragma unroll
        for (int j = 0; j < 4; j++)
            #pragma unroll
            for (int e = 0; e < 4; e++) acc[i][j][e] = 0.f;

    const __nv_bfloat16* srcs[4] = {Ahp, Alp, Bhp, Blp};

    auto load_stage = [&](int s, int k0) {
        #pragma unroll
        for (int a = 0; a < 4; a++) {
            #pragma unroll
            for (int t = 0; t < 2; t++) {
                int q   = tid + t * 256;
                int row = q >> 2, c4 = q & 3;
                int grow = (a < 2) ? (bm + row) : (bn + row);
                bool valid = (a < 2) ? (grow < M) : true;
                const __nv_bfloat16* src = srcs[a] + (long)(valid ? grow : 0) * K + k0 + c4 * 8;
                cpa16(sb + s * STG_B + a * 10240 + row * 80 + c4 * 16, src, valid);
            }
        }
    };

    load_stage(0, 0);
    CP_COMMIT();
    if (nch > 1) { load_stage(1, 32); CP_COMMIT(); }

    for (int c = 0; c < nch; c++) {
        if (c + 1 < nch) CP_WAIT(1);
        else             CP_WAIT(0);
        __syncthreads();
        if (c + 2 < nch) { load_stage((c + 2) % 3, (c + 2) * 32); CP_COMMIT(); }

        const uint32_t stb = sb + (c % 3) * STG_B;
        const uint32_t sAh = stb, sAl = stb + 10240, sBh = stb + 20480, sBl = stb + 30720;

        #pragma unroll
        for (int ks = 0; ks < 2; ks++) {
            const uint32_t kof = ks * 32;
            uint32_t bh[4][2], bl[4][2];
            #pragma unroll
            for (int jp = 0; jp < 2; jp++) {
                uint32_t ad = (uint32_t)((wn + jp * 16) * 80) + kof;
                ldsm4(&bh[jp*2][0], sBh + ad + boff);
                ldsm4(&bl[jp*2][0], sBl + ad + boff);
            }
            #pragma unroll
            for (int i = 0; i < 4; i++) {
                uint32_t ad = (uint32_t)((wm + i * 16) * 80) + kof;
                uint32_t ahf[4], alf[4];
                ldsm4(ahf, sAh + ad + aoff);
                ldsm4(alf, sAl + ad + aoff);
                #pragma unroll
                for (int j = 0; j < 4; j++) mma16816(acc[i][j], ahf, bh[j]);
                #pragma unroll
                for (int j = 0; j < 4; j++) mma16816(acc[i][j], alf, bh[j]);
                #pragma unroll
                for (int j = 0; j < 4; j++) mma16816(acc[i][j], ahf, bl[j]);
            }
        }
    }

    #pragma unroll
    for (int i = 0; i < 4; i++) {
        #pragma unroll
        for (int rr = 0; rr < 2; rr++) {
            int m = bm + wm + i * 16 + gq + rr * 8;
            if (m >= M) continue;
            #pragma unroll
            for (int j = 0; j < 4; j++) {
                int n = bn + wn + j * 8 + gt * 2;
                float v0 = acc[i][j][rr * 2 + 0] + __ldg(&bias[n]);
                float v1 = acc[i][j][rr * 2 + 1] + __ldg(&bias[n + 1]);
                if (RES) {
                    const float* rp = Rz + (long)m * N + n;
                    v0 += rp[0]; v1 += rp[1];
                }
                if (ACT) {
                    v0 = 0.5f * v0 * (1.0f + erff(v0 * 0.70710678118654752f));
                    v1 = 0.5f * v1 * (1.0f + erff(v1 * 0.70710678118654752f));
                }
                if (OMODE == 0)
                    *(float2*)(C + (long)m * N + n) = make_float2(v0, v1);
                if (OMODE == 1) {
                    __nv_bfloat16 h0,h1,l0,l1;
                    split_bf(v0,h0,l0); split_bf(v1,h1,l1);
                    *(uint32_t*)(Chp + (long)m * N + n) = pack_bf2(h0,h1);
                    *(uint32_t*)(Clp + (long)m * N + n) = pack_bf2(l0,l1);
                }
                if (OMODE == 2) {
                    __nv_bfloat16 h0,h1,l0,l1;
                    split_bf(v0,h0,l0); split_bf(v1,h1,l1);
                    Chp[(long)n * ldt + m]       = h0;
                    Chp[(long)(n + 1) * ldt + m] = h1;
                    Clp[(long)n * ldt + m]       = l0;
                    Clp[(long)(n + 1) * ldt + m] = l1;
                }
            }
        }
    }
}

// ======== fused QKV projection: N=2304, B = concatenated wq|wk|wv ============
__global__ void __launch_bounds__(256)
gemm_qkv(const __nv_bfloat16* __restrict__ Ahp, const __nv_bfloat16* __restrict__ Alp,
         const __nv_bfloat16* __restrict__ Bhp, const __nv_bfloat16* __restrict__ Blp,
         const float* __restrict__ bias3,
         __nv_bfloat16* __restrict__ qh, __nv_bfloat16* __restrict__ ql,
         __nv_bfloat16* __restrict__ kh, __nv_bfloat16* __restrict__ kl,
         __nv_bfloat16* __restrict__ vth, __nv_bfloat16* __restrict__ vtl,
         int M, int ldt)
{
    extern __shared__ char smem[];
    const uint32_t sb = smem_u32(smem);
    const int tid  = threadIdx.x;
    const int lane = tid & 31;
    const int wid  = tid >> 5;
    const int wm   = (wid & 1) * 64;
    const int wn   = (wid >> 1) * 32;
    const int bm   = blockIdx.y * 128;
    const int bn   = blockIdx.x * 128;
    const int K    = Dd;
    const int nch  = K >> 5;
    const int gq = lane >> 2;
    const int gt = lane & 3;

    const int lrow = lane & 7, lmat = lane >> 3;
    const uint32_t aoff = (uint32_t)((lrow + (lmat & 1) * 8) * 80 + (lmat >> 1) * 16);
    const uint32_t boff = (uint32_t)((lrow + (lmat >> 1) * 8) * 80 + (lmat & 1) * 16);

    float acc[4][4][4];
    #pragma unroll
    for (int i = 0; i < 4; i++)
        #pragma unroll
        for (int j = 0; j < 4; j++)
            #pragma unroll
            for (int e = 0; e < 4; e++) acc[i][j][e] = 0.f;

    const __nv_bfloat16* srcs[4] = {Ahp, Alp, Bhp, Blp};

    auto load_stage = [&](int s, int k0) {
        #pragma unroll
        for (int a = 0; a < 4; a++) {
            #pragma unroll
            for (int t = 0; t < 2; t++) {
                int q   = tid + t * 256;
                int row = q >> 2, c4 = q & 3;
                int grow = (a < 2) ? (bm + row) : (bn + row);
                const __nv_bfloat16* src = srcs[a] + (long)grow * K + k0 + c4 * 8;
                cpa16(sb + s * STG_B + a * 10240 + row * 80 + c4 * 16, src, true);
            }
        }
    };

    load_stage(0, 0);
    CP_COMMIT();
    load_stage(1, 32);
    CP_COMMIT();

    for (int c = 0; c < nch; c++) {
        if (c + 1 < nch) CP_WAIT(1);
        else             CP_WAIT(0);
        __syncthreads();
        if (c + 2 < nch) { load_stage((c + 2) % 3, (c + 2) * 32); CP_COMMIT(); }

        const uint32_t stb = sb + (c % 3) * STG_B;
        const uint32_t sAh = stb, sAl = stb + 10240, sBh = stb + 20480, sBl = stb + 30720;

        #pragma unroll
        for (int ks = 0; ks < 2; ks++) {
            const uint32_t kof = ks * 32;
            uint32_t bh[4][2], bl[4][2];
            #pragma unroll
            for (int jp = 0; jp < 2; jp++) {
                uint32_t ad = (uint32_t)((wn + jp * 16) * 80) + kof;
                ldsm4(&bh[jp*2][0], sBh + ad + boff);
                ldsm4(&bl[jp*2][0], sBl + ad + boff);
            }
            #pragma unroll
            for (int i = 0; i < 4; i++) {
                uint32_t ad = (uint32_t)((wm + i * 16) * 80) + kof;
                uint32_t ahf[4], alf[4];
                ldsm4(ahf, sAh + ad + aoff);
                ldsm4(alf, sAl + ad + aoff);
                #pragma unroll
                for (int j = 0; j < 4; j++) mma16816(acc[i][j], ahf, bh[j]);
                #pragma unroll
                for (int j = 0; j < 4; j++) mma16816(acc[i][j], alf, bh[j]);
                #pragma unroll
                for (int j = 0; j < 4; j++) mma16816(acc[i][j], ahf, bl[j]);
            }
        }
    }

    const int seg = bn / Dd;     // 0=Q, 1=K, 2=V
    #pragma unroll
    for (int i = 0; i < 4; i++) {
        #pragma unroll
        for (int rr = 0; rr < 2; rr++) {
            int m = bm + wm + i * 16 + gq + rr * 8;
            #pragma unroll
            for (int j = 0; j < 4; j++) {
                int n = bn + wn + j * 8 + gt * 2;
                float v0 = acc[i][j][rr * 2 + 0] + __ldg(&bias3[n]);
                float v1 = acc[i][j][rr * 2 + 1] + __ldg(&bias3[n + 1]);
                int ln_ = n - seg * Dd;
                __nv_bfloat16 h0,h1,l0,l1;
                split_bf(v0,h0,l0); split_bf(v1,h1,l1);
                if (seg == 0) {
                    *(uint32_t*)(qh + (long)m * Dd + ln_) = pack_bf2(h0,h1);
                    *(uint32_t*)(ql + (long)m * Dd + ln_) = pack_bf2(l0,l1);
                } else if (seg == 1) {
                    *(uint32_t*)(kh + (long)m * Dd + ln_) = pack_bf2(h0,h1);
                    *(uint32_t*)(kl + (long)m * Dd + ln_) = pack_bf2(l0,l1);
                } else {
                    vth[(long)ln_ * ldt + m]       = h0;
                    vth[(long)(ln_ + 1) * ldt + m] = h1;
                    vtl[(long)ln_ * ldt + m]       = l0;
                    vtl[(long)(ln_ + 1) * ldt + m] = l1;
                }
            }
        }
    }
}

// ============ tensor-core flash attention (split bf16) =======================
// 128 threads (4 warps x 16 q-rows = 64 q-rows/CTA), K-tile 64, 3-stage KV ring.
#define ATS   144
#define AROWB 9216
#define ASTG0 (2*AROWB)
#define ASTGSZ (4*AROWB)
#define ASMEM (ASTG0 + 3*ASTGSZ)  // 129024

__global__ void __launch_bounds__(128)
attn_mma(const __nv_bfloat16* __restrict__ Qh, const __nv_bfloat16* __restrict__ Ql,
         const __nv_bfloat16* __restrict__ Kh, const __nv_bfloat16* __restrict__ Kl,
         const __nv_bfloat16* __restrict__ Vth, const __nv_bfloat16* __restrict__ Vtl,
         __nv_bfloat16* __restrict__ Oh, __nv_bfloat16* __restrict__ Ol,
         int Sk, int kvRowPB, int vtColPB, int ldv, int band)
{
    extern __shared__ char sm[];
    const uint32_t sb = smem_u32(sm);
    const int tid = threadIdx.x;
    const int wq  = tid >> 5;
    const int lane = tid & 31;
    const int gq = lane >> 2, gt = lane & 3;
    const int b = blockIdx.z, h = blockIdx.y, q0 = blockIdx.x * 64;

    const int lrow = lane & 7, lmat = lane >> 3;
    const uint32_t aoffA = (uint32_t)((lrow + (lmat & 1) * 8) * ATS + (lmat >> 1) * 16);
    const uint32_t boffA = (uint32_t)((lrow + (lmat >> 1) * 8) * ATS + (lmat & 1) * 16);

    // Q tile (loaded once, grouped with KV stage 0)
    {
        const __nv_bfloat16* qsrc[2] = {Qh, Ql};
        #pragma unroll
        for (int a = 0; a < 2; a++) {
            const __nv_bfloat16* src = qsrc[a] + ((long)(b * Ss + q0)) * Dd + h * DHd;
            #pragma unroll
            for (int it = 0; it < 4; it++) {
                int idx = it * 128 + tid, row = idx >> 3, c4 = idx & 7;
                cpa16(sb + a * AROWB + row * ATS + c4 * 16, src + (long)row * Dd + c4 * 8, true);
            }
        }
    }
    auto loadKV = [&](int stg, int k0) {
        uint32_t so = sb + ASTG0 + (stg % 3) * ASTGSZ;
        const __nv_bfloat16* ks[2] = {Kh, Kl};
        #pragma unroll
        for (int a = 0; a < 2; a++) {
            const __nv_bfloat16* src = ks[a] + ((long)(kvRowPB * b + k0)) * Dd + h * DHd;
            #pragma unroll
            for (int it = 0; it < 4; it++) {
                int idx = it * 128 + tid, row = idx >> 3, c4 = idx & 7;
                cpa16(so + a * AROWB + row * ATS + c4 * 16, src + (long)row * Dd + c4 * 8, true);
            }
        }
        const __nv_bfloat16* vs[2] = {Vth, Vtl};
        #pragma unroll
        for (int a = 0; a < 2; a++) {
            const __nv_bfloat16* src = vs[a] + (long)(h * DHd) * ldv + (long)vtColPB * b + k0;
            #pragma unroll
            for (int it = 0; it < 4; it++) {
                int idx = it * 128 + tid, row = idx >> 3, c4 = idx & 7;
                cpa16(so + (2 + a) * AROWB + row * ATS + c4 * 16, src + (long)row * ldv + c4 * 8, true);
            }
        }
    };
    const int nkt = Sk >> 6;
    loadKV(0, 0);
    CP_COMMIT();
    if (nkt > 1) { loadKV(1, 64); CP_COMMIT(); }

    float m0 = -1e30f, m1 = -1e30f, l0 = 0.f, l1 = 0.f;
    float o[8][4];
    #pragma unroll
    for (int j = 0; j < 8; j++)
        #pragma unroll
        for (int e = 0; e < 4; e++) o[j][e] = 0.f;
    uint32_t qfh[4][4], qfl[4][4];

    for (int t = 0; t < nkt; t++) {
        if (t + 1 < nkt) CP_WAIT(1);
        else             CP_WAIT(0);
        __syncthreads();
        if (t + 2 < nkt) { loadKV(t + 2, (t + 2) * 64); CP_COMMIT(); }

        if (t == 0) {
            const uint32_t qb0 = sb + (uint32_t)(wq * 16 * ATS);
            #pragma unroll
            for (int s = 0; s < 4; s++) {
                ldsm4(qfh[s], qb0 + s * 32 + aoffA);
                ldsm4(qfl[s], qb0 + AROWB + s * 32 + aoffA);
            }
        }

        const uint32_t stb = sb + ASTG0 + (t % 3) * ASTGSZ;
        const uint32_t sKh = stb, sKl = stb + AROWB;
        const uint32_t sVh = stb + 2 * AROWB, sVl = stb + 3 * AROWB;

        // ---- scores S = Q K^T  (two jp-tiles interleaved: 4 indep accs) ----
        float sc[8][4];
        #pragma unroll
        for (int j = 0; j < 8; j++)
            #pragma unroll
            for (int e = 0; e < 4; e++) sc[j][e] = 0.f;

        #pragma unroll
        for (int jpp = 0; jpp < 2; jpp++) {
            uint32_t ad0 = (uint32_t)((jpp * 2)     * 16 * ATS);
            uint32_t ad1 = (uint32_t)((jpp * 2 + 1) * 16 * ATS);
            int j0 = 4 * jpp;
            #pragma unroll
            for (int s = 0; s < 4; s++) {
                uint32_t kha[4], kla[4], khb[4], klb[4];
                ldsm4(kha, sKh + ad0 + s * 32 + boffA);
                ldsm4(kla, sKl + ad0 + s * 32 + boffA);
                ldsm4(khb, sKh + ad1 + s * 32 + boffA);
                ldsm4(klb, sKl + ad1 + s * 32 + boffA);
                mma16816(sc[j0+0], qfh[s], &kha[0]);
                mma16816(sc[j0+1], qfh[s], &kha[2]);
                mma16816(sc[j0+2], qfh[s], &khb[0]);
                mma16816(sc[j0+3], qfh[s], &khb[2]);
                mma16816(sc[j0+0], qfl[s], &kha[0]);
                mma16816(sc[j0+1], qfl[s], &kha[2]);
                mma16816(sc[j0+2], qfl[s], &khb[0]);
                mma16816(sc[j0+3], qfl[s], &khb[2]);
                mma16816(sc[j0+0], qfh[s], &kla[0]);
                mma16816(sc[j0+1], qfh[s], &kla[2]);
                mma16816(sc[j0+2], qfh[s], &klb[0]);
                mma16816(sc[j0+3], qfh[s], &klb[2]);
            }
        }

        const int k0 = t * 64;
        const int qi0 = q0 + wq * 16 + gq, qi1 = qi0 + 8;
        #pragma unroll
        for (int j = 0; j < 8; j++) {
            int ki0 = k0 + j * 8 + gt * 2, ki1 = ki0 + 1;
            if (band) {
                int d00 = qi0 - ki0; d00 = d00 < 0 ? -d00 : d00;
                int d01 = qi0 - ki1; d01 = d01 < 0 ? -d01 : d01;
                int d10 = qi1 - ki0; d10 = d10 < 0 ? -d10 : d10;
                int d11 = qi1 - ki1; d11 = d11 < 0 ? -d11 : d11;
                sc[j][0] = sc[j][0] * 0.125f + (d00 <= Rr ? 1.f : 0.f);
                sc[j][1] = sc[j][1] * 0.125f + (d01 <= Rr ? 1.f : 0.f);
                sc[j][2] = sc[j][2] * 0.125f + (d10 <= Rr ? 1.f : 0.f);
                sc[j][3] = sc[j][3] * 0.125f + (d11 <= Rr ? 1.f : 0.f);
            } else {
                sc[j][0] *= 0.125f; sc[j][1] *= 0.125f;
                sc[j][2] *= 0.125f; sc[j][3] *= 0.125f;
            }
        }

        // ---- online softmax ----
        float nm0 = -1e30f, nm1 = -1e30f;
        #pragma unroll
        for (int j = 0; j < 8; j++) {
            nm0 = fmaxf(nm0, fmaxf(sc[j][0], sc[j][1]));
            nm1 = fmaxf(nm1, fmaxf(sc[j][2], sc[j][3]));
        }
        nm0 = fmaxf(nm0, __shfl_xor_sync(0xffffffffu, nm0, 1));
        nm0 = fmaxf(nm0, __shfl_xor_sync(0xffffffffu, nm0, 2));
        nm1 = fmaxf(nm1, __shfl_xor_sync(0xffffffffu, nm1, 1));
        nm1 = fmaxf(nm1, __shfl_xor_sync(0xffffffffu, nm1, 2));
        float M0 = fmaxf(m0, nm0), M1 = fmaxf(m1, nm1);
        float f0 = __expf(m0 - M0), f1 = __expf(m1 - M1);
        m0 = M0; m1 = M1;

        float s0 = 0.f, s1 = 0.f;
        #pragma unroll
        for (int j = 0; j < 8; j++) {
            sc[j][0] = __expf(sc[j][0] - M0);
            sc[j][1] = __expf(sc[j][1] - M0);
            sc[j][2] = __expf(sc[j][2] - M1);
            sc[j][3] = __expf(sc[j][3] - M1);
            s0 += sc[j][0] + sc[j][1];
            s1 += sc[j][2] + sc[j][3];
        }
        s0 += __shfl_xor_sync(0xffffffffu, s0, 1);
        s0 += __shfl_xor_sync(0xffffffffu, s0, 2);
        s1 += __shfl_xor_sync(0xffffffffu, s1, 1);
        s1 += __shfl_xor_sync(0xffffffffu, s1, 2);
        l0 = l0 * f0 + s0;
        l1 = l1 * f1 + s1;

        #pragma unroll
        for (int j = 0; j < 8; j++) {
            o[j][0] *= f0; o[j][1] *= f0;
            o[j][2] *= f1; o[j][3] *= f1;
        }

        // ---- P fragments (bf16 hi/lo) ----
        uint32_t ph[4][4], pl[4][4];
        #pragma unroll
        for (int s = 0; s < 4; s++) {
            __nv_bfloat16 h0,h1,lo0,lo1;
            split_bf(sc[2*s][0], h0, lo0); split_bf(sc[2*s][1], h1, lo1);
            ph[s][0] = pack_bf2(h0,h1); pl[s][0] = pack_bf2(lo0,lo1);
            split_bf(sc[2*s][2], h0, lo0); split_bf(sc[2*s][3], h1, lo1);
            ph[s][1] = pack_bf2(h0,h1); pl[s][1] = pack_bf2(lo0,lo1);
            split_bf(sc[2*s+1][0], h0, lo0); split_bf(sc[2*s+1][1], h1, lo1);
            ph[s][2] = pack_bf2(h0,h1); pl[s][2] = pack_bf2(lo0,lo1);
            split_bf(sc[2*s+1][2], h0, lo0); split_bf(sc[2*s+1][3], h1, lo1);
            ph[s][3] = pack_bf2(h0,h1); pl[s][3] = pack_bf2(lo0,lo1);
        }

        // ---- O += P V  (two jp-tiles interleaved) ----
        #pragma unroll
        for (int jpp = 0; jpp < 2; jpp++) {
            uint32_t ad0 = (uint32_t)((jpp * 2)     * 16 * ATS);
            uint32_t ad1 = (uint32_t)((jpp * 2 + 1) * 16 * ATS);
            int j0 = 4 * jpp;
            #pragma unroll
            for (int s = 0; s < 4; s++) {
                uint32_t vha[4], vla[4], vhb[4], vlb[4];
                ldsm4(vha, sVh + ad0 + s * 32 + boffA);
                ldsm4(vla, sVl + ad0 + s * 32 + boffA);
                ldsm4(vhb, sVh + ad1 + s * 32 + boffA);
                ldsm4(vlb, sVl + ad1 + s * 32 + boffA);
                mma16816(o[j0+0], ph[s], &vha[0]);
                mma16816(o[j0+1], ph[s], &vha[2]);
                mma16816(o[j0+2], ph[s], &vhb[0]);
                mma16816(o[j0+3], ph[s], &vhb[2]);
                mma16816(o[j0+0], pl[s], &vha[0]);
                mma16816(o[j0+1], pl[s], &vha[2]);
                mma16816(o[j0+2], pl[s], &vhb[0]);
                mma16816(o[j0+3], pl[s], &vhb[2]);
                mma16816(o[j0+0], ph[s], &vla[0]);
                mma16816(o[j0+1], ph[s], &vla[2]);
                mma16816(o[j0+2], ph[s], &vlb[0]);
                mma16816(o[j0+3], ph[s], &vlb[2]);
            }
        }
    }

    // ---- write ctx as bf16 hi/lo ----
    float i0 = 1.f / l0, i1 = 1.f / l1;
    long r0g = (long)(b * Ss) + q0 + wq * 16 + gq;
    #pragma unroll
    for (int jd = 0; jd < 8; jd++) {
        int col = h * DHd + jd * 8 + gt * 2;
        float v0 = o[jd][0] * i0, v1 = o[jd][1] * i0;
        float v2 = o[jd][2] * i1, v3 = o[jd][3] * i1;
        __nv_bfloat16 h0,h1,lo0,lo1;
        split_bf(v0,h0,lo0); split_bf(v1,h1,lo1);
        *(uint32_t*)(Oh + r0g * Dd + col) = pack_bf2(h0,h1);
        *(uint32_t*)(Ol + r0g * Dd + col) = pack_bf2(lo0,lo1);
        split_bf(v2,h0,lo0); split_bf(v3,h1,lo1);
        *(uint32_t*)(Oh + (r0g + 8) * Dd + col) = pack_bf2(h0,h1);
        *(uint32_t*)(Ol + (r0g + 8) * Dd + col) = pack_bf2(lo0,lo1);
    }
}

// ---------------- LayerNorm ---------------------------------------------
__global__ __launch_bounds__(256)
void ln_kernel(const float* __restrict__ in, const float* __restrict__ g,
               const float* __restrict__ bta, float* __restrict__ out,
               __nv_bfloat16* __restrict__ oh, __nv_bfloat16* __restrict__ ol)
{
    const int row = blockIdx.x;
    const float* x = in + (long)row * Dd;
    const int tid = threadIdx.x;

    float v0 = x[tid], v1 = x[tid + 256], v2 = x[tid + 512];
    float s = v0 + v1 + v2;

    __shared__ float sred[8];
    __shared__ float smean, svar;

    #pragma unroll
    for (int off = 16; off; off >>= 1) s += __shfl_xor_sync(0xffffffffu, s, off);
    if ((tid & 31) == 0) sred[tid >> 5] = s;
    __syncthreads();
    if (tid == 0) {
        float t = 0.f;
        #pragma unroll
        for (int i = 0; i < 8; i++) t += sred[i];
        smean = t * (1.0f / Dd);
    }
    __syncthreads();
    float m = smean;
    float d0 = v0 - m, d1 = v1 - m, d2 = v2 - m;
    float sq = d0*d0 + d1*d1 + d2*d2;
    #pragma unroll
    for (int off = 16; off; off >>= 1) sq += __shfl_xor_sync(0xffffffffu, sq, off);
    if ((tid & 31) == 0) sred[tid >> 5] = sq;
    __syncthreads();
    if (tid == 0) {
        float t = 0.f;
        #pragma unroll
        for (int i = 0; i < 8; i++) t += sred[i];
        svar = t * (1.0f / Dd);
    }
    __syncthreads();
    float inv = rsqrtf(svar + 1e-12f);
    #pragma unroll
    for (int u = 0; u < 3; u++) {
        int idx = tid + u * 256;
        float d = (u == 0 ? d0 : (u == 1 ? d1 : d2));
        float val = d * inv * g[idx] + bta[idx];
        out[(long)row * Dd + idx] = val;
        if (oh) {
            __nv_bfloat16 hh, ll; split_bf(val, hh, ll);
            oh[(long)row * Dd + idx] = hh;
            ol[(long)row * Dd + idx] = ll;
        }
    }
}

// ---------------- launch ----------------------------------------------------
typedef void (*gemm_fn)(const __nv_bfloat16*, const __nv_bfloat16*,
                        const __nv_bfloat16*, const __nv_bfloat16*,
                        const float*, const float*,
                        float*, __nv_bfloat16*, __nv_bfloat16*, int, int, int, int);

static inline void launch_gemm_t(gemm_fn fn,
                                 const __nv_bfloat16* Ah, const __nv_bfloat16* Al,
                                 const __nv_bfloat16* Bh, const __nv_bfloat16* Bl,
                                 const float* bias, const float* Rz,
                                 float* C, __nv_bfloat16* Ch, __nv_bfloat16* Cl,
                                 int M, int N, int K, int ldt)
{
    dim3 g(N / 128, (M + 127) / 128);
    cudaFuncSetAttribute((const void*)fn, cudaFuncAttributeMaxDynamicSharedMemorySize, 3 * STG_B);
    fn<<<g, 256, 3 * STG_B>>>(Ah, Al, Bh, Bl, bias, Rz, C, Ch, Cl, M, N, K, ldt);
}

extern "C" void kernel_launch(void* const* d_in, const int* in_sizes, int n_in,
                              void* d_out, int out_size)
{
    const float* X     = (const float*)d_in[0];
    const float* tag   = (const float*)d_in[1];
    const float* sa_wq = (const float*)d_in[2];  const float* sa_bq = (const float*)d_in[3];
    const float* sa_wk = (const float*)d_in[4];  const float* sa_bk = (const float*)d_in[5];
    const float* sa_wv = (const float*)d_in[6];  const float* sa_bv = (const float*)d_in[7];
    const float* sa_wo = (const float*)d_in[8];  const float* sa_bo = (const float*)d_in[9];
    const float* sa_lg = (const float*)d_in[10]; const float* sa_lb = (const float*)d_in[11];
    const float* ca_wq = (const float*)d_in[12]; const float* ca_bq = (const float*)d_in[13];
    const float* ca_wk = (const float*)d_in[14]; const float* ca_bk = (const float*)d_in[15];
    const float* ca_wv = (const float*)d_in[16]; const float* ca_bv = (const float*)d_in[17];
    const float* ca_wo = (const float*)d_in[18]; const float* ca_bo = (const float*)d_in[19];
    const float* ca_lg = (const float*)d_in[20]; const float* ca_lb = (const float*)d_in[21];
    const float* ff_w1 = (const float*)d_in[22]; const float* ff_b1 = (const float*)d_in[23];
    const float* ff_w2 = (const float*)d_in[24]; const float* ff_b2 = (const float*)d_in[25];
    const float* ff_lg = (const float*)d_in[26]; const float* ff_lb = (const float*)d_in[27];
    float* out = (float*)d_out;

    float *t1, *x1, *x2, *b3;
    cudaGetSymbolAddress((void**)&t1, g_t1);
    cudaGetSymbolAddress((void**)&x1, g_x1); cudaGetSymbolAddress((void**)&x2, g_x2);
    cudaGetSymbolAddress((void**)&b3, g_b3);

    __nv_bfloat16 *xh,*xl,*x1h,*x1l,*x2h,*x2l,*cth,*ctl,*ffh,*ffl,*tgh,*tgl,*wh,*wl;
    __nv_bfloat16 *qh,*ql,*kh,*kl,*vth,*vtl,*ckh,*ckl,*cvth,*cvtl;
    cudaGetSymbolAddress((void**)&xh,  g_xh);  cudaGetSymbolAddress((void**)&xl,  g_xl);
    cudaGetSymbolAddress((void**)&x1h, g_x1h); cudaGetSymbolAddress((void**)&x1l, g_x1l);
    cudaGetSymbolAddress((void**)&x2h, g_x2h); cudaGetSymbolAddress((void**)&x2l, g_x2l);
    cudaGetSymbolAddress((void**)&cth, g_cth); cudaGetSymbolAddress((void**)&ctl, g_ctl);
    cudaGetSymbolAddress((void**)&ffh, g_ffh); cudaGetSymbolAddress((void**)&ffl, g_ffl);
    cudaGetSymbolAddress((void**)&tgh, g_tgh); cudaGetSymbolAddress((void**)&tgl, g_tgl);
    cudaGetSymbolAddress((void**)&wh,  g_wh);  cudaGetSymbolAddress((void**)&wl,  g_wl);
    cudaGetSymbolAddress((void**)&qh,  g_qh);  cudaGetSymbolAddress((void**)&ql,  g_ql);
    cudaGetSymbolAddress((void**)&kh,  g_kh);  cudaGetSymbolAddress((void**)&kl,  g_kl);
    cudaGetSymbolAddress((void**)&vth, g_vth); cudaGetSymbolAddress((void**)&vtl, g_vtl);
    cudaGetSymbolAddress((void**)&ckh, g_ckh); cudaGetSymbolAddress((void**)&ckl, g_ckl);
    cudaGetSymbolAddress((void**)&cvth,g_cvth);cudaGetSymbolAddress((void**)&cvtl,g_cvtl);

    const int M = MTOT;
    dim3 agrid(Ss / 64, Hh, Bb);   // (32, 12, 2)
    dim3 tb(32, 8);

    cudaFuncSetAttribute(attn_mma, cudaFuncAttributeMaxDynamicSharedMemorySize, ASMEM);
    cudaFuncSetAttribute(gemm_qkv, cudaFuncAttributeMaxDynamicSharedMemorySize, 3 * STG_B);

    // ---- pre-convert activations, biases & weights ----
    fconv<<<(M*Dd/4 + 255)/256, 256>>>(X, xh, xl, M*Dd/4);
    fconv<<<(Tt*Dd/4 + 255)/256, 256>>>(tag, tgh, tgl, Tt*Dd/4);
    bcat3<<<9, 256>>>(sa_bq, sa_bk, sa_bv, b3);

    {
        const float* ws[10]  = {sa_wq, sa_wk, sa_wv, sa_wo, ca_wq, ca_wk, ca_wv, ca_wo, ff_w1, ff_w2};
        const long  woff[10] = {0, WSZ, 2*WSZ, 3*WSZ, 4*WSZ, 5*WSZ, 6*WSZ, 7*WSZ, WOFF_FF1, WOFF_FF2};
        const int   wk_[10]  = {Dd,Dd,Dd,Dd,Dd,Dd,Dd,Dd,Dd,FFd};
        const int   wn_[10]  = {Dd,Dd,Dd,Dd,Dd,Dd,Dd,Dd,FFd,Dd};
        WAll wa;
        int cum = 0;
        for (int i = 0; i < 10; i++) {
            wa.W[i] = ws[i]; wa.Wh[i] = wh + woff[i]; wa.Wl[i] = wl + woff[i];
            wa.K[i] = wk_[i]; wa.N[i] = wn_[i]; wa.t0[i] = cum;
            cum += (wk_[i] / 32) * (wn_[i] / 32);
        }
        wtconv_all<<<cum, tb>>>(wa);
    }

    // ---- self-attention (fused QKV projection) ----
    {
        dim3 g(3 * Dd / 128, M / 128);   // 18 x 32 = 576 CTAs
        gemm_qkv<<<g, 256, 3 * STG_B>>>(xh, xl, wh, wl, b3,
                                        qh, ql, kh, kl, vth, vtl, M, MTOT);
    }
    attn_mma<<<agrid, 128, ASMEM>>>(qh, ql, kh, kl, vth, vtl, cth, ctl, Ss, Ss, Ss, MTOT, 1);
    launch_gemm_t(gemm_bf<0,1,0>, cth, ctl, wh+3*WSZ, wl+3*WSZ, sa_bo, X, t1, nullptr, nullptr, M, Dd, Dd, 0);
    ln_kernel<<<M, 256>>>(t1, sa_lg, sa_lb, x1, x1h, x1l);

    // ---- cross-attention ----
    launch_gemm_t(gemm_bf<0,0,1>, x1h, x1l, wh+4*WSZ, wl+4*WSZ, ca_bq, nullptr, nullptr, qh, ql, M, Dd, Dd, 0);
    launch_gemm_t(gemm_bf<0,0,1>, tgh, tgl, wh+5*WSZ, wl+5*WSZ, ca_bk, nullptr, nullptr, ckh, ckl, Tt, Dd, Dd, 0);
    launch_gemm_t(gemm_bf<0,0,2>, tgh, tgl, wh+6*WSZ, wl+6*WSZ, ca_bv, nullptr, nullptr, cvth, cvtl, Tt, Dd, Dd, Tt);
    attn_mma<<<agrid, 128, ASMEM>>>(qh, ql, ckh, ckl, cvth, cvtl, cth, ctl, Tt, 0, 0, Tt, 0);
    launch_gemm_t(gemm_bf<0,1,0>, cth, ctl, wh+7*WSZ, wl+7*WSZ, ca_bo, x1, t1, nullptr, nullptr, M, Dd, Dd, 0);
    ln_kernel<<<M, 256>>>(t1, ca_lg, ca_lb, x2, x2h, x2l);

    // ---- FFN ----
    launch_gemm_t(gemm_bf<1,0,1>, x2h, x2l, wh+WOFF_FF1, wl+WOFF_FF1, ff_b1, nullptr, nullptr, ffh, ffl, M, FFd, Dd, 0);
    launch_gemm_t(gemm_bf<0,1,0>, ffh, ffl, wh+WOFF_FF2, wl+WOFF_FF2, ff_b2, x2, t1, nullptr, nullptr, M, Dd, FFd, 0);
    ln_kernel<<<M, 256>>>(t1, ff_lg, ff_lb, out, nullptr, nullptr);
}

// round 17
// speedup vs baseline: 1.2070x; 1.2070x over previous
#include <cuda_runtime.h>
#include <cuda_bf16.h>
#include <math.h>
#include <cstdint>

// Problem constants
#define Bb   2
#define Ss   2048
#define Dd   768
#define Hh   12
#define DHd  64
#define Tt   64
#define FFd  3072
#define Rr   50

#define MTOT (Bb*Ss)        // 4096

// ---------------- scratch (device globals; no allocations allowed) ----------
__device__ float g_t1 [MTOT*Dd];
__device__ float g_x1 [MTOT*Dd];
__device__ float g_x2 [MTOT*Dd];
__device__ float g_b3 [3*Dd];

// bf16 hi/lo buffers
__device__ __nv_bfloat16 g_xh [MTOT*Dd],  g_xl [MTOT*Dd];
__device__ __nv_bfloat16 g_x1h[MTOT*Dd],  g_x1l[MTOT*Dd];
__device__ __nv_bfloat16 g_x2h[MTOT*Dd],  g_x2l[MTOT*Dd];
__device__ __nv_bfloat16 g_cth[MTOT*Dd],  g_ctl[MTOT*Dd];
__device__ __nv_bfloat16 g_ffh[MTOT*FFd], g_ffl[MTOT*FFd];
__device__ __nv_bfloat16 g_tgh[Tt*Dd],    g_tgl[Tt*Dd];
__device__ __nv_bfloat16 g_qh [MTOT*Dd],  g_ql [MTOT*Dd];
__device__ __nv_bfloat16 g_kh [MTOT*Dd],  g_kl [MTOT*Dd];
__device__ __nv_bfloat16 g_vth[Dd*MTOT],  g_vtl[Dd*MTOT];   // V^T [n][m]
__device__ __nv_bfloat16 g_ckh[Tt*Dd],    g_ckl[Tt*Dd];
__device__ __nv_bfloat16 g_cvth[Dd*Tt],   g_cvtl[Dd*Tt];    // cross V^T

// transposed weights [N][K] hi/lo; wq,wk,wv contiguous -> fused QKV B = [2304][768]
#define WSZ  (Dd*Dd)
#define WOFF_FF1 (8*WSZ)
#define WOFF_FF2 (WOFF_FF1 + Dd*FFd)
#define WTOT (WOFF_FF2 + FFd*Dd)
__device__ __nv_bfloat16 g_wh[WTOT], g_wl[WTOT];

// =============== helpers =====================================================
__device__ __forceinline__ void mma16816(float* c, const uint32_t* a, const uint32_t* b) {
    asm volatile(
        "mma.sync.aligned.m16n8k16.row.col.f32.bf16.bf16.f32 "
        "{%0,%1,%2,%3}, {%4,%5,%6,%7}, {%8,%9}, {%0,%1,%2,%3};\n"
        : "+f"(c[0]), "+f"(c[1]), "+f"(c[2]), "+f"(c[3])
        : "r"(a[0]), "r"(a[1]), "r"(a[2]), "r"(a[3]), "r"(b[0]), "r"(b[1]));
}
__device__ __forceinline__ void ldsm4(uint32_t* r, uint32_t addr) {
    asm volatile("ldmatrix.sync.aligned.m8n8.x4.shared.b16 {%0,%1,%2,%3}, [%4];"
                 : "=r"(r[0]), "=r"(r[1]), "=r"(r[2]), "=r"(r[3]) : "r"(addr));
}
__device__ __forceinline__ uint32_t pack_bf2(__nv_bfloat16 a, __nv_bfloat16 b) {
    return ((uint32_t)__bfloat16_as_ushort(b) << 16) | (uint32_t)__bfloat16_as_ushort(a);
}
__device__ __forceinline__ uint32_t smem_u32(const void* p) {
    uint32_t a;
    asm("{ .reg .u64 t; cvta.to.shared.u64 t, %1; cvt.u32.u64 %0, t; }" : "=r"(a) : "l"(p));
    return a;
}
__device__ __forceinline__ void cpa16(uint32_t dst, const void* src, bool valid) {
    int sz = valid ? 16 : 0;
    asm volatile("cp.async.cg.shared.global [%0], [%1], 16, %2;"
                 :: "r"(dst), "l"(src), "r"(sz));
}
#define CP_COMMIT() asm volatile("cp.async.commit_group;" ::: "memory")
#define CP_WAIT(n)  asm volatile("cp.async.wait_group %0;" :: "n"(n) : "memory")

__device__ __forceinline__ void split_bf(float v, __nv_bfloat16& h, __nv_bfloat16& l) {
    h = __float2bfloat16(v);
    l = __float2bfloat16(v - __bfloat162float(h));
}

// ============ conversion kernels ============================================
__global__ void fconv(const float* __restrict__ x, __nv_bfloat16* __restrict__ h,
                      __nv_bfloat16* __restrict__ l, int n4)
{
    int i = blockIdx.x * 256 + threadIdx.x;
    if (i >= n4) return;
    float4 v = ((const float4*)x)[i];
    __nv_bfloat16 h0,h1,h2,h3,l0,l1,l2,l3;
    split_bf(v.x,h0,l0); split_bf(v.y,h1,l1); split_bf(v.z,h2,l2); split_bf(v.w,h3,l3);
    ((uint2*)h)[i] = make_uint2(pack_bf2(h0,h1), pack_bf2(h2,h3));
    ((uint2*)l)[i] = make_uint2(pack_bf2(l0,l1), pack_bf2(l2,l3));
}

__global__ void bcat3(const float* __restrict__ b0, const float* __restrict__ b1,
                      const float* __restrict__ b2, float* __restrict__ o)
{
    int i = blockIdx.x * 256 + threadIdx.x;
    if (i < Dd)            o[i] = b0[i];
    else if (i < 2*Dd)     o[i] = b1[i - Dd];
    else if (i < 3*Dd)     o[i] = b2[i - 2*Dd];
}

// fused weight transpose+split for all 10 weights in one launch
struct WAll {
    const float* W[10];
    __nv_bfloat16* Wh[10];
    __nv_bfloat16* Wl[10];
    int K[10], N[10], t0[10];
};

__global__ void wtconv_all(WAll d)
{
    __shared__ float t[32][33];
    const int bid = blockIdx.x;
    int w = 0;
    #pragma unroll
    for (int i = 1; i < 10; i++) if (bid >= d.t0[i]) w = i;
    const int K = d.K[w], N = d.N[w];
    const int tloc = bid - d.t0[w];
    const int nx = N >> 5;
    const int n0 = (tloc % nx) * 32, k0 = (tloc / nx) * 32;
    const float* W = d.W[w];
    __nv_bfloat16* Wh = d.Wh[w];
    __nv_bfloat16* Wl = d.Wl[w];

    const int tx = threadIdx.x, ty = threadIdx.y;   // 32 x 8
    #pragma unroll
    for (int i = 0; i < 4; i++)
        t[ty + i*8][tx] = W[(long)(k0 + ty + i*8) * N + n0 + tx];
    __syncthreads();
    #pragma unroll
    for (int i = 0; i < 4; i++) {
        int n = n0 + ty + i*8;
        float v = t[tx][ty + i*8];
        __nv_bfloat16 h, l; split_bf(v, h, l);
        Wh[(long)n * K + k0 + tx] = h;
        Wl[(long)n * K + k0 + tx] = l;
    }
}

// ======== split-bf16 tensor-core GEMM ========================================
// 256 threads, 8 warps (2m x 4n), warp tile 32x32, CTA tile 64x128, BK=32.
// 2-stage cp.async double buffer; stage = Ah(5120) Al(5120) Bh(10240) Bl(10240)
// = 30720 B -> 2 stages 61440 B -> 2 CTAs/SM resident.
// OMODE: 0 = fp32 C, 1 = bf16 hi/lo, 2 = bf16 hi/lo TRANSPOSED [n][m] (ldt)
#define STG_B 30720

template<int ACT, int RES, int OMODE>
__global__ void __launch_bounds__(256)
gemm_bf(const __nv_bfloat16* __restrict__ Ahp, const __nv_bfloat16* __restrict__ Alp,
        const __nv_bfloat16* __restrict__ Bhp, const __nv_bfloat16* __restrict__ Blp,
        const float* __restrict__ bias, const float* __restrict__ Rz,
        float* __restrict__ C, __nv_bfloat16* __restrict__ Chp, __nv_bfloat16* __restrict__ Clp,
        int M, int N, int K, int ldt)
{
    extern __shared__ char smem[];
    const uint32_t sb = smem_u32(smem);
    const int tid  = threadIdx.x;
    const int lane = tid & 31;
    const int wid  = tid >> 5;
    const int wm   = (wid & 1) * 32;
    const int wn   = (wid >> 1) * 32;
    const int bm   = blockIdx.y * 64;
    const int bn   = blockIdx.x * 128;
    const int nch  = K >> 5;
    const int gq = lane >> 2;
    const int gt = lane & 3;

    const int lrow = lane & 7, lmat = lane >> 3;
    const uint32_t aoff = (uint32_t)((lrow + (lmat & 1) * 8) * 80 + (lmat >> 1) * 16);
    const uint32_t boff = (uint32_t)((lrow + (lmat >> 1) * 8) * 80 + (lmat & 1) * 16);

    float acc[2][4][4];
    #pragma unroll
    for (int i = 0; i < 2; i++)
        #pragma unroll
        for (int j = 0; j < 4; j++)
            #pragma unroll
            for (int e = 0; e < 4; e++) acc[i][j][e] = 0.f;

    const __nv_bfloat16* srcs[4] = {Ahp, Alp, Bhp, Blp};

    // stage layout: Ah @0 (64*80), Al @5120, Bh @10240 (128*80), Bl @20480
    auto load_stage = [&](int s, int k0) {
        // A arrays: 64 rows x 4 seg = 256 -> 1 per thread
        {
            int row = tid >> 2, c4 = tid & 3;
            int grow = bm + row;
            bool valid = grow < M;
            #pragma unroll
            for (int a = 0; a < 2; a++) {
                const __nv_bfloat16* src = srcs[a] + (long)(valid ? grow : 0) * K + k0 + c4 * 8;
                cpa16(sb + s * STG_B + a * 5120 + row * 80 + c4 * 16, src, valid);
            }
        }
        // B arrays: 128 rows x 4 seg = 512 -> 2 per thread
        #pragma unroll
        for (int a = 0; a < 2; a++) {
            #pragma unroll
            for (int t = 0; t < 2; t++) {
                int q = tid + t * 256;
                int row = q >> 2, c4 = q & 3;
                const __nv_bfloat16* src = srcs[2 + a] + (long)(bn + row) * K + k0 + c4 * 8;
                cpa16(sb + s * STG_B + 10240 + a * 10240 + row * 80 + c4 * 16, src, true);
            }
        }
    };

    load_stage(0, 0);
    CP_COMMIT();

    for (int c = 0; c < nch; c++) {
        if (c + 1 < nch) { load_stage((c + 1) & 1, (c + 1) * 32); CP_COMMIT(); CP_WAIT(1); }
        else             { CP_WAIT(0); }
        __syncthreads();

        const uint32_t stb = sb + (c & 1) * STG_B;
        const uint32_t sAh = stb, sAl = stb + 5120, sBh = stb + 10240, sBl = stb + 20480;

        #pragma unroll
        for (int ks = 0; ks < 2; ks++) {
            const uint32_t kof = ks * 32;
            uint32_t bh[4][2], bl[4][2];
            #pragma unroll
            for (int jp = 0; jp < 2; jp++) {
                uint32_t ad = (uint32_t)((wn + jp * 16) * 80) + kof;
                ldsm4(&bh[jp*2][0], sBh + ad + boff);
                ldsm4(&bl[jp*2][0], sBl + ad + boff);
            }
            #pragma unroll
            for (int i = 0; i < 2; i++) {
                uint32_t ad = (uint32_t)((wm + i * 16) * 80) + kof;
                uint32_t ahf[4], alf[4];
                ldsm4(ahf, sAh + ad + aoff);
                ldsm4(alf, sAl + ad + aoff);
                #pragma unroll
                for (int j = 0; j < 4; j++) mma16816(acc[i][j], ahf, bh[j]);
                #pragma unroll
                for (int j = 0; j < 4; j++) mma16816(acc[i][j], alf, bh[j]);
                #pragma unroll
                for (int j = 0; j < 4; j++) mma16816(acc[i][j], ahf, bl[j]);
            }
        }
        __syncthreads();
    }

    #pragma unroll
    for (int i = 0; i < 2; i++) {
        #pragma unroll
        for (int rr = 0; rr < 2; rr++) {
            int m = bm + wm + i * 16 + gq + rr * 8;
            if (m >= M) continue;
            #pragma unroll
            for (int j = 0; j < 4; j++) {
                int n = bn + wn + j * 8 + gt * 2;
                float v0 = acc[i][j][rr * 2 + 0] + __ldg(&bias[n]);
                float v1 = acc[i][j][rr * 2 + 1] + __ldg(&bias[n + 1]);
                if (RES) {
                    const float* rp = Rz + (long)m * N + n;
                    v0 += rp[0]; v1 += rp[1];
                }
                if (ACT) {
                    v0 = 0.5f * v0 * (1.0f + erff(v0 * 0.70710678118654752f));
                    v1 = 0.5f * v1 * (1.0f + erff(v1 * 0.70710678118654752f));
                }
                if (OMODE == 0)
                    *(float2*)(C + (long)m * N + n) = make_float2(v0, v1);
                if (OMODE == 1) {
                    __nv_bfloat16 h0,h1,l0,l1;
                    split_bf(v0,h0,l0); split_bf(v1,h1,l1);
                    *(uint32_t*)(Chp + (long)m * N + n) = pack_bf2(h0,h1);
                    *(uint32_t*)(Clp + (long)m * N + n) = pack_bf2(l0,l1);
                }
                if (OMODE == 2) {
                    __nv_bfloat16 h0,h1,l0,l1;
                    split_bf(v0,h0,l0); split_bf(v1,h1,l1);
                    Chp[(long)n * ldt + m]       = h0;
                    Chp[(long)(n + 1) * ldt + m] = h1;
                    Clp[(long)n * ldt + m]       = l0;
                    Clp[(long)(n + 1) * ldt + m] = l1;
                }
            }
        }
    }
}

// ======== fused QKV projection: N=2304, B = concatenated wq|wk|wv ============
__global__ void __launch_bounds__(256)
gemm_qkv(const __nv_bfloat16* __restrict__ Ahp, const __nv_bfloat16* __restrict__ Alp,
         const __nv_bfloat16* __restrict__ Bhp, const __nv_bfloat16* __restrict__ Blp,
         const float* __restrict__ bias3,
         __nv_bfloat16* __restrict__ qh, __nv_bfloat16* __restrict__ ql,
         __nv_bfloat16* __restrict__ kh, __nv_bfloat16* __restrict__ kl,
         __nv_bfloat16* __restrict__ vth, __nv_bfloat16* __restrict__ vtl,
         int M, int ldt)
{
    extern __shared__ char smem[];
    const uint32_t sb = smem_u32(smem);
    const int tid  = threadIdx.x;
    const int lane = tid & 31;
    const int wid  = tid >> 5;
    const int wm   = (wid & 1) * 32;
    const int wn   = (wid >> 1) * 32;
    const int bm   = blockIdx.y * 64;
    const int bn   = blockIdx.x * 128;
    const int K    = Dd;
    const int nch  = K >> 5;
    const int gq = lane >> 2;
    const int gt = lane & 3;

    const int lrow = lane & 7, lmat = lane >> 3;
    const uint32_t aoff = (uint32_t)((lrow + (lmat & 1) * 8) * 80 + (lmat >> 1) * 16);
    const uint32_t boff = (uint32_t)((lrow + (lmat >> 1) * 8) * 80 + (lmat & 1) * 16);

    float acc[2][4][4];
    #pragma unroll
    for (int i = 0; i < 2; i++)
        #pragma unroll
        for (int j = 0; j < 4; j++)
            #pragma unroll
            for (int e = 0; e < 4; e++) acc[i][j][e] = 0.f;

    const __nv_bfloat16* srcs[4] = {Ahp, Alp, Bhp, Blp};

    auto load_stage = [&](int s, int k0) {
        {
            int row = tid >> 2, c4 = tid & 3;
            int grow = bm + row;
            #pragma unroll
            for (int a = 0; a < 2; a++) {
                const __nv_bfloat16* src = srcs[a] + (long)grow * K + k0 + c4 * 8;
                cpa16(sb + s * STG_B + a * 5120 + row * 80 + c4 * 16, src, true);
            }
        }
        #pragma unroll
        for (int a = 0; a < 2; a++) {
            #pragma unroll
            for (int t = 0; t < 2; t++) {
                int q = tid + t * 256;
                int row = q >> 2, c4 = q & 3;
                const __nv_bfloat16* src = srcs[2 + a] + (long)(bn + row) * K + k0 + c4 * 8;
                cpa16(sb + s * STG_B + 10240 + a * 10240 + row * 80 + c4 * 16, src, true);
            }
        }
    };

    load_stage(0, 0);
    CP_COMMIT();

    for (int c = 0; c < nch; c++) {
        if (c + 1 < nch) { load_stage((c + 1) & 1, (c + 1) * 32); CP_COMMIT(); CP_WAIT(1); }
        else             { CP_WAIT(0); }
        __syncthreads();

        const uint32_t stb = sb + (c & 1) * STG_B;
        const uint32_t sAh = stb, sAl = stb + 5120, sBh = stb + 10240, sBl = stb + 20480;

        #pragma unroll
        for (int ks = 0; ks < 2; ks++) {
            const uint32_t kof = ks * 32;
            uint32_t bh[4][2], bl[4][2];
            #pragma unroll
            for (int jp = 0; jp < 2; jp++) {
                uint32_t ad = (uint32_t)((wn + jp * 16) * 80) + kof;
                ldsm4(&bh[jp*2][0], sBh + ad + boff);
                ldsm4(&bl[jp*2][0], sBl + ad + boff);
            }
            #pragma unroll
            for (int i = 0; i < 2; i++) {
                uint32_t ad = (uint32_t)((wm + i * 16) * 80) + kof;
                uint32_t ahf[4], alf[4];
                ldsm4(ahf, sAh + ad + aoff);
                ldsm4(alf, sAl + ad + aoff);
                #pragma unroll
                for (int j = 0; j < 4; j++) mma16816(acc[i][j], ahf, bh[j]);
                #pragma unroll
                for (int j = 0; j < 4; j++) mma16816(acc[i][j], alf, bh[j]);
                #pragma unroll
                for (int j = 0; j < 4; j++) mma16816(acc[i][j], ahf, bl[j]);
            }
        }
        __syncthreads();
    }

    const int seg = bn / Dd;     // 0=Q, 1=K, 2=V  (128-tiles never straddle)
    #pragma unroll
    for (int i = 0; i < 2; i++) {
        #pragma unroll
        for (int rr = 0; rr < 2; rr++) {
            int m = bm + wm + i * 16 + gq + rr * 8;
            #pragma unroll
            for (int j = 0; j < 4; j++) {
                int n = bn + wn + j * 8 + gt * 2;
                float v0 = acc[i][j][rr * 2 + 0] + __ldg(&bias3[n]);
                float v1 = acc[i][j][rr * 2 + 1] + __ldg(&bias3[n + 1]);
                int ln_ = n - seg * Dd;
                __nv_bfloat16 h0,h1,l0,l1;
                split_bf(v0,h0,l0); split_bf(v1,h1,l1);
                if (seg == 0) {
                    *(uint32_t*)(qh + (long)m * Dd + ln_) = pack_bf2(h0,h1);
                    *(uint32_t*)(ql + (long)m * Dd + ln_) = pack_bf2(l0,l1);
                } else if (seg == 1) {
                    *(uint32_t*)(kh + (long)m * Dd + ln_) = pack_bf2(h0,h1);
                    *(uint32_t*)(kl + (long)m * Dd + ln_) = pack_bf2(l0,l1);
                } else {
                    vth[(long)ln_ * ldt + m]       = h0;
                    vth[(long)(ln_ + 1) * ldt + m] = h1;
                    vtl[(long)ln_ * ldt + m]       = l0;
                    vtl[(long)(ln_ + 1) * ldt + m] = l1;
                }
            }
        }
    }
}

// ============ tensor-core flash attention (split bf16) =======================
// Exact R9 configuration: 128 threads, 64 q-rows, K-tile 64, 2-stage KV buffer.
#define ATS   144
#define AROWB 9216
#define ASTG0 (2*AROWB)
#define ASTGSZ (4*AROWB)
#define ASMEM (ASTG0 + 2*ASTGSZ)  // 92160

__global__ void __launch_bounds__(128)
attn_mma(const __nv_bfloat16* __restrict__ Qh, const __nv_bfloat16* __restrict__ Ql,
         const __nv_bfloat16* __restrict__ Kh, const __nv_bfloat16* __restrict__ Kl,
         const __nv_bfloat16* __restrict__ Vth, const __nv_bfloat16* __restrict__ Vtl,
         __nv_bfloat16* __restrict__ Oh, __nv_bfloat16* __restrict__ Ol,
         int Sk, int kvRowPB, int vtColPB, int ldv, int band)
{
    extern __shared__ char sm[];
    const uint32_t sb = smem_u32(sm);
    const int tid = threadIdx.x;
    const int wq  = tid >> 5;
    const int lane = tid & 31;
    const int gq = lane >> 2, gt = lane & 3;
    const int b = blockIdx.z, h = blockIdx.y, q0 = blockIdx.x * 64;

    const int lrow = lane & 7, lmat = lane >> 3;
    const uint32_t aoffA = (uint32_t)((lrow + (lmat & 1) * 8) * ATS + (lmat >> 1) * 16);
    const uint32_t boffA = (uint32_t)((lrow + (lmat >> 1) * 8) * ATS + (lmat & 1) * 16);

    // Q tile (loaded once)
    {
        const __nv_bfloat16* qsrc[2] = {Qh, Ql};
        #pragma unroll
        for (int a = 0; a < 2; a++) {
            const __nv_bfloat16* src = qsrc[a] + ((long)(b * Ss + q0)) * Dd + h * DHd;
            #pragma unroll
            for (int it = 0; it < 4; it++) {
                int idx = it * 128 + tid, row = idx >> 3, c4 = idx & 7;
                cpa16(sb + a * AROWB + row * ATS + c4 * 16, src + (long)row * Dd + c4 * 8, true);
            }
        }
    }
    auto loadKV = [&](int stg, int k0) {
        uint32_t so = sb + ASTG0 + (stg & 1) * ASTGSZ;
        const __nv_bfloat16* ks[2] = {Kh, Kl};
        #pragma unroll
        for (int a = 0; a < 2; a++) {
            const __nv_bfloat16* src = ks[a] + ((long)(kvRowPB * b + k0)) * Dd + h * DHd;
            #pragma unroll
            for (int it = 0; it < 4; it++) {
                int idx = it * 128 + tid, row = idx >> 3, c4 = idx & 7;
                cpa16(so + a * AROWB + row * ATS + c4 * 16, src + (long)row * Dd + c4 * 8, true);
            }
        }
        const __nv_bfloat16* vs[2] = {Vth, Vtl};
        #pragma unroll
        for (int a = 0; a < 2; a++) {
            const __nv_bfloat16* src = vs[a] + (long)(h * DHd) * ldv + (long)vtColPB * b + k0;
            #pragma unroll
            for (int it = 0; it < 4; it++) {
                int idx = it * 128 + tid, row = idx >> 3, c4 = idx & 7;
                cpa16(so + (2 + a) * AROWB + row * ATS + c4 * 16, src + (long)row * ldv + c4 * 8, true);
            }
        }
    };
    loadKV(0, 0);
    CP_COMMIT();

    float m0 = -1e30f, m1 = -1e30f, l0 = 0.f, l1 = 0.f;
    float o[8][4];
    #pragma unroll
    for (int j = 0; j < 8; j++)
        #pragma unroll
        for (int e = 0; e < 4; e++) o[j][e] = 0.f;
    uint32_t qfh[4][4], qfl[4][4];

    const int nkt = Sk >> 6;
    for (int t = 0; t < nkt; t++) {
        if (t + 1 < nkt) { loadKV(t + 1, (t + 1) * 64); CP_COMMIT(); CP_WAIT(1); }
        else             { CP_WAIT(0); }
        __syncthreads();

        if (t == 0) {
            const uint32_t qb0 = sb + (uint32_t)(wq * 16 * ATS);
            #pragma unroll
            for (int s = 0; s < 4; s++) {
                ldsm4(qfh[s], qb0 + s * 32 + aoffA);
                ldsm4(qfl[s], qb0 + AROWB + s * 32 + aoffA);
            }
        }

        const uint32_t stb = sb + ASTG0 + (t & 1) * ASTGSZ;
        const uint32_t sKh = stb, sKl = stb + AROWB;
        const uint32_t sVh = stb + 2 * AROWB, sVl = stb + 3 * AROWB;

        // ---- scores S = Q K^T  (two jp-tiles interleaved: 4 indep accs) ----
        float sc[8][4];
        #pragma unroll
        for (int j = 0; j < 8; j++)
            #pragma unroll
            for (int e = 0; e < 4; e++) sc[j][e] = 0.f;

        #pragma unroll
        for (int jpp = 0; jpp < 2; jpp++) {
            uint32_t ad0 = (uint32_t)((jpp * 2)     * 16 * ATS);
            uint32_t ad1 = (uint32_t)((jpp * 2 + 1) * 16 * ATS);
            int j0 = 4 * jpp;
            #pragma unroll
            for (int s = 0; s < 4; s++) {
                uint32_t kha[4], kla[4], khb[4], klb[4];
                ldsm4(kha, sKh + ad0 + s * 32 + boffA);
                ldsm4(kla, sKl + ad0 + s * 32 + boffA);
                ldsm4(khb, sKh + ad1 + s * 32 + boffA);
                ldsm4(klb, sKl + ad1 + s * 32 + boffA);
                mma16816(sc[j0+0], qfh[s], &kha[0]);
                mma16816(sc[j0+1], qfh[s], &kha[2]);
                mma16816(sc[j0+2], qfh[s], &khb[0]);
                mma16816(sc[j0+3], qfh[s], &khb[2]);
                mma16816(sc[j0+0], qfl[s], &kha[0]);
                mma16816(sc[j0+1], qfl[s], &kha[2]);
                mma16816(sc[j0+2], qfl[s], &khb[0]);
                mma16816(sc[j0+3], qfl[s], &khb[2]);
                mma16816(sc[j0+0], qfh[s], &kla[0]);
                mma16816(sc[j0+1], qfh[s], &kla[2]);
                mma16816(sc[j0+2], qfh[s], &klb[0]);
                mma16816(sc[j0+3], qfh[s], &klb[2]);
            }
        }

        const int k0 = t * 64;
        const int qi0 = q0 + wq * 16 + gq, qi1 = qi0 + 8;
        #pragma unroll
        for (int j = 0; j < 8; j++) {
            int ki0 = k0 + j * 8 + gt * 2, ki1 = ki0 + 1;
            if (band) {
                int d00 = qi0 - ki0; d00 = d00 < 0 ? -d00 : d00;
                int d01 = qi0 - ki1; d01 = d01 < 0 ? -d01 : d01;
                int d10 = qi1 - ki0; d10 = d10 < 0 ? -d10 : d10;
                int d11 = qi1 - ki1; d11 = d11 < 0 ? -d11 : d11;
                sc[j][0] = sc[j][0] * 0.125f + (d00 <= Rr ? 1.f : 0.f);
                sc[j][1] = sc[j][1] * 0.125f + (d01 <= Rr ? 1.f : 0.f);
                sc[j][2] = sc[j][2] * 0.125f + (d10 <= Rr ? 1.f : 0.f);
                sc[j][3] = sc[j][3] * 0.125f + (d11 <= Rr ? 1.f : 0.f);
            } else {
                sc[j][0] *= 0.125f; sc[j][1] *= 0.125f;
                sc[j][2] *= 0.125f; sc[j][3] *= 0.125f;
            }
        }

        // ---- online softmax ----
        float nm0 = -1e30f, nm1 = -1e30f;
        #pragma unroll
        for (int j = 0; j < 8; j++) {
            nm0 = fmaxf(nm0, fmaxf(sc[j][0], sc[j][1]));
            nm1 = fmaxf(nm1, fmaxf(sc[j][2], sc[j][3]));
        }
        nm0 = fmaxf(nm0, __shfl_xor_sync(0xffffffffu, nm0, 1));
        nm0 = fmaxf(nm0, __shfl_xor_sync(0xffffffffu, nm0, 2));
        nm1 = fmaxf(nm1, __shfl_xor_sync(0xffffffffu, nm1, 1));
        nm1 = fmaxf(nm1, __shfl_xor_sync(0xffffffffu, nm1, 2));
        float M0 = fmaxf(m0, nm0), M1 = fmaxf(m1, nm1);
        float f0 = __expf(m0 - M0), f1 = __expf(m1 - M1);
        m0 = M0; m1 = M1;

        float s0 = 0.f, s1 = 0.f;
        #pragma unroll
        for (int j = 0; j < 8; j++) {
            sc[j][0] = __expf(sc[j][0] - M0);
            sc[j][1] = __expf(sc[j][1] - M0);
            sc[j][2] = __expf(sc[j][2] - M1);
            sc[j][3] = __expf(sc[j][3] - M1);
            s0 += sc[j][0] + sc[j][1];
            s1 += sc[j][2] + sc[j][3];
        }
        s0 += __shfl_xor_sync(0xffffffffu, s0, 1);
        s0 += __shfl_xor_sync(0xffffffffu, s0, 2);
        s1 += __shfl_xor_sync(0xffffffffu, s1, 1);
        s1 += __shfl_xor_sync(0xffffffffu, s1, 2);
        l0 = l0 * f0 + s0;
        l1 = l1 * f1 + s1;

        #pragma unroll
        for (int j = 0; j < 8; j++) {
            o[j][0] *= f0; o[j][1] *= f0;
            o[j][2] *= f1; o[j][3] *= f1;
        }

        // ---- P fragments (bf16 hi/lo) ----
        uint32_t ph[4][4], pl[4][4];
        #pragma unroll
        for (int s = 0; s < 4; s++) {
            __nv_bfloat16 h0,h1,lo0,lo1;
            split_bf(sc[2*s][0], h0, lo0); split_bf(sc[2*s][1], h1, lo1);
            ph[s][0] = pack_bf2(h0,h1); pl[s][0] = pack_bf2(lo0,lo1);
            split_bf(sc[2*s][2], h0, lo0); split_bf(sc[2*s][3], h1, lo1);
            ph[s][1] = pack_bf2(h0,h1); pl[s][1] = pack_bf2(lo0,lo1);
            split_bf(sc[2*s+1][0], h0, lo0); split_bf(sc[2*s+1][1], h1, lo1);
            ph[s][2] = pack_bf2(h0,h1); pl[s][2] = pack_bf2(lo0,lo1);
            split_bf(sc[2*s+1][2], h0, lo0); split_bf(sc[2*s+1][3], h1, lo1);
            ph[s][3] = pack_bf2(h0,h1); pl[s][3] = pack_bf2(lo0,lo1);
        }

        // ---- O += P V  (two jp-tiles interleaved) ----
        #pragma unroll
        for (int jpp = 0; jpp < 2; jpp++) {
            uint32_t ad0 = (uint32_t)((jpp * 2)     * 16 * ATS);
            uint32_t ad1 = (uint32_t)((jpp * 2 + 1) * 16 * ATS);
            int j0 = 4 * jpp;
            #pragma unroll
            for (int s = 0; s < 4; s++) {
                uint32_t vha[4], vla[4], vhb[4], vlb[4];
                ldsm4(vha, sVh + ad0 + s * 32 + boffA);
                ldsm4(vla, sVl + ad0 + s * 32 + boffA);
                ldsm4(vhb, sVh + ad1 + s * 32 + boffA);
                ldsm4(vlb, sVl + ad1 + s * 32 + boffA);
                mma16816(o[j0+0], ph[s], &vha[0]);
                mma16816(o[j0+1], ph[s], &vha[2]);
                mma16816(o[j0+2], ph[s], &vhb[0]);
                mma16816(o[j0+3], ph[s], &vhb[2]);
                mma16816(o[j0+0], pl[s], &vha[0]);
                mma16816(o[j0+1], pl[s], &vha[2]);
                mma16816(o[j0+2], pl[s], &vhb[0]);
                mma16816(o[j0+3], pl[s], &vhb[2]);
                mma16816(o[j0+0], ph[s], &vla[0]);
                mma16816(o[j0+1], ph[s], &vla[2]);
                mma16816(o[j0+2], ph[s], &vlb[0]);
                mma16816(o[j0+3], ph[s], &vlb[2]);
            }
        }
        __syncthreads();
    }

    // ---- write ctx as bf16 hi/lo ----
    float i0 = 1.f / l0, i1 = 1.f / l1;
    long r0g = (long)(b * Ss) + q0 + wq * 16 + gq;
    #pragma unroll
    for (int jd = 0; jd < 8; jd++) {
        int col = h * DHd + jd * 8 + gt * 2;
        float v0 = o[jd][0] * i0, v1 = o[jd][1] * i0;
        float v2 = o[jd][2] * i1, v3 = o[jd][3] * i1;
        __nv_bfloat16 h0,h1,lo0,lo1;
        split_bf(v0,h0,lo0); split_bf(v1,h1,lo1);
        *(uint32_t*)(Oh + r0g * Dd + col) = pack_bf2(h0,h1);
        *(uint32_t*)(Ol + r0g * Dd + col) = pack_bf2(lo0,lo1);
        split_bf(v2,h0,lo0); split_bf(v3,h1,lo1);
        *(uint32_t*)(Oh + (r0g + 8) * Dd + col) = pack_bf2(h0,h1);
        *(uint32_t*)(Ol + (r0g + 8) * Dd + col) = pack_bf2(lo0,lo1);
    }
}

// ---------------- LayerNorm ---------------------------------------------
__global__ __launch_bounds__(256)
void ln_kernel(const float* __restrict__ in, const float* __restrict__ g,
               const float* __restrict__ bta, float* __restrict__ out,
               __nv_bfloat16* __restrict__ oh, __nv_bfloat16* __restrict__ ol)
{
    const int row = blockIdx.x;
    const float* x = in + (long)row * Dd;
    const int tid = threadIdx.x;

    float v0 = x[tid], v1 = x[tid + 256], v2 = x[tid + 512];
    float s = v0 + v1 + v2;

    __shared__ float sred[8];
    __shared__ float smean, svar;

    #pragma unroll
    for (int off = 16; off; off >>= 1) s += __shfl_xor_sync(0xffffffffu, s, off);
    if ((tid & 31) == 0) sred[tid >> 5] = s;
    __syncthreads();
    if (tid == 0) {
        float t = 0.f;
        #pragma unroll
        for (int i = 0; i < 8; i++) t += sred[i];
        smean = t * (1.0f / Dd);
    }
    __syncthreads();
    float m = smean;
    float d0 = v0 - m, d1 = v1 - m, d2 = v2 - m;
    float sq = d0*d0 + d1*d1 + d2*d2;
    #pragma unroll
    for (int off = 16; off; off >>= 1) sq += __shfl_xor_sync(0xffffffffu, sq, off);
    if ((tid & 31) == 0) sred[tid >> 5] = sq;
    __syncthreads();
    if (tid == 0) {
        float t = 0.f;
        #pragma unroll
        for (int i = 0; i < 8; i++) t += sred[i];
        svar = t * (1.0f / Dd);
    }
    __syncthreads();
    float inv = rsqrtf(svar + 1e-12f);
    #pragma unroll
    for (int u = 0; u < 3; u++) {
        int idx = tid + u * 256;
        float d = (u == 0 ? d0 : (u == 1 ? d1 : d2));
        float val = d * inv * g[idx] + bta[idx];
        out[(long)row * Dd + idx] = val;
        if (oh) {
            __nv_bfloat16 hh, ll; split_bf(val, hh, ll);
            oh[(long)row * Dd + idx] = hh;
            ol[(long)row * Dd + idx] = ll;
        }
    }
}

// ---------------- launch ----------------------------------------------------
typedef void (*gemm_fn)(const __nv_bfloat16*, const __nv_bfloat16*,
                        const __nv_bfloat16*, const __nv_bfloat16*,
                        const float*, const float*,
                        float*, __nv_bfloat16*, __nv_bfloat16*, int, int, int, int);

static inline void launch_gemm_t(gemm_fn fn,
                                 const __nv_bfloat16* Ah, const __nv_bfloat16* Al,
                                 const __nv_bfloat16* Bh, const __nv_bfloat16* Bl,
                                 const float* bias, const float* Rz,
                                 float* C, __nv_bfloat16* Ch, __nv_bfloat16* Cl,
                                 int M, int N, int K, int ldt)
{
    dim3 g(N / 128, (M + 63) / 64);
    cudaFuncSetAttribute((const void*)fn, cudaFuncAttributeMaxDynamicSharedMemorySize, 2 * STG_B);
    fn<<<g, 256, 2 * STG_B>>>(Ah, Al, Bh, Bl, bias, Rz, C, Ch, Cl, M, N, K, ldt);
}

extern "C" void kernel_launch(void* const* d_in, const int* in_sizes, int n_in,
                              void* d_out, int out_size)
{
    const float* X     = (const float*)d_in[0];
    const float* tag   = (const float*)d_in[1];
    const float* sa_wq = (const float*)d_in[2];  const float* sa_bq = (const float*)d_in[3];
    const float* sa_wk = (const float*)d_in[4];  const float* sa_bk = (const float*)d_in[5];
    const float* sa_wv = (const float*)d_in[6];  const float* sa_bv = (const float*)d_in[7];
    const float* sa_wo = (const float*)d_in[8];  const float* sa_bo = (const float*)d_in[9];
    const float* sa_lg = (const float*)d_in[10]; const float* sa_lb = (const float*)d_in[11];
    const float* ca_wq = (const float*)d_in[12]; const float* ca_bq = (const float*)d_in[13];
    const float* ca_wk = (const float*)d_in[14]; const float* ca_bk = (const float*)d_in[15];
    const float* ca_wv = (const float*)d_in[16]; const float* ca_bv = (const float*)d_in[17];
    const float* ca_wo = (const float*)d_in[18]; const float* ca_bo = (const float*)d_in[19];
    const float* ca_lg = (const float*)d_in[20]; const float* ca_lb = (const float*)d_in[21];
    const float* ff_w1 = (const float*)d_in[22]; const float* ff_b1 = (const float*)d_in[23];
    const float* ff_w2 = (const float*)d_in[24]; const float* ff_b2 = (const float*)d_in[25];
    const float* ff_lg = (const float*)d_in[26]; const float* ff_lb = (const float*)d_in[27];
    float* out = (float*)d_out;

    float *t1, *x1, *x2, *b3;
    cudaGetSymbolAddress((void**)&t1, g_t1);
    cudaGetSymbolAddress((void**)&x1, g_x1); cudaGetSymbolAddress((void**)&x2, g_x2);
    cudaGetSymbolAddress((void**)&b3, g_b3);

    __nv_bfloat16 *xh,*xl,*x1h,*x1l,*x2h,*x2l,*cth,*ctl,*ffh,*ffl,*tgh,*tgl,*wh,*wl;
    __nv_bfloat16 *qh,*ql,*kh,*kl,*vth,*vtl,*ckh,*ckl,*cvth,*cvtl;
    cudaGetSymbolAddress((void**)&xh,  g_xh);  cudaGetSymbolAddress((void**)&xl,  g_xl);
    cudaGetSymbolAddress((void**)&x1h, g_x1h); cudaGetSymbolAddress((void**)&x1l, g_x1l);
    cudaGetSymbolAddress((void**)&x2h, g_x2h); cudaGetSymbolAddress((void**)&x2l, g_x2l);
    cudaGetSymbolAddress((void**)&cth, g_cth); cudaGetSymbolAddress((void**)&ctl, g_ctl);
    cudaGetSymbolAddress((void**)&ffh, g_ffh); cudaGetSymbolAddress((void**)&ffl, g_ffl);
    cudaGetSymbolAddress((void**)&tgh, g_tgh); cudaGetSymbolAddress((void**)&tgl, g_tgl);
    cudaGetSymbolAddress((void**)&wh,  g_wh);  cudaGetSymbolAddress((void**)&wl,  g_wl);
    cudaGetSymbolAddress((void**)&qh,  g_qh);  cudaGetSymbolAddress((void**)&ql,  g_ql);
    cudaGetSymbolAddress((void**)&kh,  g_kh);  cudaGetSymbolAddress((void**)&kl,  g_kl);
    cudaGetSymbolAddress((void**)&vth, g_vth); cudaGetSymbolAddress((void**)&vtl, g_vtl);
    cudaGetSymbolAddress((void**)&ckh, g_ckh); cudaGetSymbolAddress((void**)&ckl, g_ckl);
    cudaGetSymbolAddress((void**)&cvth,g_cvth);cudaGetSymbolAddress((void**)&cvtl,g_cvtl);

    const int M = MTOT;
    dim3 agrid(Ss / 64, Hh, Bb);   // (32, 12, 2)
    dim3 tb(32, 8);

    cudaFuncSetAttribute(attn_mma, cudaFuncAttributeMaxDynamicSharedMemorySize, ASMEM);
    cudaFuncSetAttribute(gemm_qkv, cudaFuncAttributeMaxDynamicSharedMemorySize, 2 * STG_B);

    // ---- pre-convert activations, biases & weights ----
    fconv<<<(M*Dd/4 + 255)/256, 256>>>(X, xh, xl, M*Dd/4);
    fconv<<<(Tt*Dd/4 + 255)/256, 256>>>(tag, tgh, tgl, Tt*Dd/4);
    bcat3<<<9, 256>>>(sa_bq, sa_bk, sa_bv, b3);

    {
        const float* ws[10]  = {sa_wq, sa_wk, sa_wv, sa_wo, ca_wq, ca_wk, ca_wv, ca_wo, ff_w1, ff_w2};
        const long  woff[10] = {0, WSZ, 2*WSZ, 3*WSZ, 4*WSZ, 5*WSZ, 6*WSZ, 7*WSZ, WOFF_FF1, WOFF_FF2};
        const int   wk_[10]  = {Dd,Dd,Dd,Dd,Dd,Dd,Dd,Dd,Dd,FFd};
        const int   wn_[10]  = {Dd,Dd,Dd,Dd,Dd,Dd,Dd,Dd,FFd,Dd};
        WAll wa;
        int cum = 0;
        for (int i = 0; i < 10; i++) {
            wa.W[i] = ws[i]; wa.Wh[i] = wh + woff[i]; wa.Wl[i] = wl + woff[i];
            wa.K[i] = wk_[i]; wa.N[i] = wn_[i]; wa.t0[i] = cum;
            cum += (wk_[i] / 32) * (wn_[i] / 32);
        }
        wtconv_all<<<cum, tb>>>(wa);
    }

    // ---- self-attention (fused QKV projection) ----
    {
        dim3 g(3 * Dd / 128, M / 64);   // 18 x 64 = 1152 CTAs
        gemm_qkv<<<g, 256, 2 * STG_B>>>(xh, xl, wh, wl, b3,
                                        qh, ql, kh, kl, vth, vtl, M, MTOT);
    }
    attn_mma<<<agrid, 128, ASMEM>>>(qh, ql, kh, kl, vth, vtl, cth, ctl, Ss, Ss, Ss, MTOT, 1);
    launch_gemm_t(gemm_bf<0,1,0>, cth, ctl, wh+3*WSZ, wl+3*WSZ, sa_bo, X, t1, nullptr, nullptr, M, Dd, Dd, 0);
    ln_kernel<<<M, 256>>>(t1, sa_lg, sa_lb, x1, x1h, x1l);

    // ---- cross-attention ----
    launch_gemm_t(gemm_bf<0,0,1>, x1h, x1l, wh+4*WSZ, wl+4*WSZ, ca_bq, nullptr, nullptr, qh, ql, M, Dd, Dd, 0);
    launch_gemm_t(gemm_bf<0,0,1>, tgh, tgl, wh+5*WSZ, wl+5*WSZ, ca_bk, nullptr, nullptr, ckh, ckl, Tt, Dd, Dd, 0);
    launch_gemm_t(gemm_bf<0,0,2>, tgh, tgl, wh+6*WSZ, wl+6*WSZ, ca_bv, nullptr, nullptr, cvth, cvtl, Tt, Dd, Dd, Tt);
    attn_mma<<<agrid, 128, ASMEM>>>(qh, ql, ckh, ckl, cvth, cvtl, cth, ctl, Tt, 0, 0, Tt, 0);
    launch_gemm_t(gemm_bf<0,1,0>, cth, ctl, wh+7*WSZ, wl+7*WSZ, ca_bo, x1, t1, nullptr, nullptr, M, Dd, Dd, 0);
    ln_kernel<<<M, 256>>>(t1, ca_lg, ca_lb, x2, x2h, x2l);

    // ---- FFN ----
    launch_gemm_t(gemm_bf<1,0,1>, x2h, x2l, wh+WOFF_FF1, wl+WOFF_FF1, ff_b1, nullptr, nullptr, ffh, ffl, M, FFd, Dd, 0);
    launch_gemm_t(gemm_bf<0,1,0>, ffh, ffl, wh+WOFF_FF2, wl+WOFF_FF2, ff_b2, x2, t1, nullptr, nullptr, M, Dd, FFd, 0);
    ln_kernel<<<M, 256>>>(t1, ff_lg, ff_lb, out, nullptr, nullptr);
}